// round 13
// baseline (speedup 1.0000x reference)
#include <cuda_runtime.h>
#include <cstdint>

// Problem constants
#define CCk 128
#define DDk 32
#define SSk 4096

// ---------------- smem byte layout (82KB -> 2 CTAs/SM) ----------------
// Stages: s*32KB, s in {0,1}: hi [128 rows][64 cols] bf16 (16KB) + lo (+16KB).
// E f32 [64][132] at 0 — aliases stage 0 (stages dead when E live).
// A_hi at 65536: two 8KB blocks by (m>>6), rows = this CTA's 64 channels.
// inv[64] f32 at 81920.
#define STAGE(s)  ((uint32_t)(s) * 32768u)
#define ESTR      132
#define AOFF      65536u
#define IVOFF     81920u
#define SMEMSZ    (IVOFF + 384u)

#define SWZ(o) ((o) ^ (((o) >> 3) & 0x70u))

static __device__ __forceinline__ uint32_t s2u(const void* p) {
    uint32_t a;
    asm("{ .reg .u64 t; cvta.to.shared.u64 t, %1; cvt.u32.u64 %0, t; }"
        : "=r"(a) : "l"(p));
    return a;
}

static __device__ __forceinline__ void ldsm4(uint32_t* r, uint32_t addr) {
    asm volatile("ldmatrix.sync.aligned.m8n8.x4.shared.b16 {%0,%1,%2,%3}, [%4];"
        : "=r"(r[0]), "=r"(r[1]), "=r"(r[2]), "=r"(r[3]) : "r"(addr));
}
static __device__ __forceinline__ void ldsm4t(uint32_t* r, uint32_t addr) {
    asm volatile("ldmatrix.sync.aligned.m8n8.x4.trans.shared.b16 {%0,%1,%2,%3}, [%4];"
        : "=r"(r[0]), "=r"(r[1]), "=r"(r[2]), "=r"(r[3]) : "r"(addr));
}
static __device__ __forceinline__ void mma16816(float* c, const uint32_t* a,
                                                uint32_t b0, uint32_t b1) {
    asm volatile(
        "mma.sync.aligned.m16n8k16.row.col.f32.bf16.bf16.f32 "
        "{%0,%1,%2,%3}, {%4,%5,%6,%7}, {%8,%9}, {%0,%1,%2,%3};"
        : "+f"(c[0]), "+f"(c[1]), "+f"(c[2]), "+f"(c[3])
        : "r"(a[0]), "r"(a[1]), "r"(a[2]), "r"(a[3]), "r"(b0), "r"(b1));
}

static __device__ __forceinline__ void split2(float f0, float f1, uint32_t& hp, uint32_t& lp) {
    asm("cvt.rn.bf16x2.f32 %0, %1, %2;" : "=r"(hp) : "f"(f1), "f"(f0));
    float h0 = __uint_as_float(hp << 16);
    float h1 = __uint_as_float(hp & 0xffff0000u);
    asm("cvt.rn.bf16x2.f32 %0, %1, %2;" : "=r"(lp) : "f"(f1 - h1), "f"(f0 - h0));
}
static __device__ __forceinline__ uint32_t pack2hi(float f0, float f1) {
    uint32_t hp;
    asm("cvt.rn.bf16x2.f32 %0, %1, %2;" : "=r"(hp) : "f"(f1), "f"(f0));
    return hp;
}
static __device__ __forceinline__ void split8(float4 a, float4 b, uint4& hi, uint4& lo) {
    split2(a.x, a.y, hi.x, lo.x);
    split2(a.z, a.w, hi.y, lo.y);
    split2(b.x, b.y, hi.z, lo.z);
    split2(b.z, b.w, hi.w, lo.w);
}
static __device__ __forceinline__ float2 bfpair(uint32_t w) {
    float2 r;
    r.x = __uint_as_float(w << 16);
    r.y = __uint_as_float(w & 0xffff0000u);
    return r;
}

__global__ __launch_bounds__(256, 2)
void cam_mma7_kernel(const float* __restrict__ x,
                     const float* __restrict__ gamma,
                     float* __restrict__ out)
{
    extern __shared__ __align__(1024) uint8_t sm[];
    const uint32_t smb = s2u(sm);

    const int tid  = threadIdx.x;
    const int lane = tid & 31;
    const int wid  = tid >> 5;

    const int hc = blockIdx.x & 1;        // which channel half this CTA owns
    const int n  = blockIdx.x >> 1;
    const int b = n / DDk, d = n % DDk;
    const float* xbase = x + ((size_t)(b * CCk) * DDk + d) * (size_t)SSk;
    const size_t cstride = (size_t)DDk * SSk;
    float* outbase = out + (size_t)n * CCk * SSk;

    // conversion mapping: 256 threads -> 128 V rows x 2 col-halves
    const int r = tid >> 1, h = tid & 1;
    const float* rowp = xbase + (size_t)r * cstride;

    // ===== Phase 1: E rows [64hc,64hc+64) x all 128. 4 tiles 32x64, 2 warps/tile k-split =====
    const int pr = wid >> 1;          // tile 0..3
    const int h1 = wid & 1;           // k-half
    const int tm = pr & 1;            // m 32-block within the 64
    const int tn = pr >> 1;           // n 64-block
    const int m0abs = hc * 64 + tm * 32;
    const int n0 = tn * 64;

    float acc[2][8][4];
#pragma unroll
    for (int mt = 0; mt < 2; mt++)
#pragma unroll
        for (int nt = 0; nt < 8; nt++)
#pragma unroll
            for (int q = 0; q < 4; q++) acc[mt][nt][q] = 0.f;

    float4 pf[8];
#pragma unroll
    for (int p = 0; p < 8; p++)
        pf[p] = *reinterpret_cast<const float4*>(rowp + h * 32 + p * 4);

    for (int kc = 0; kc < 64; kc++) {
        uint8_t* hb = sm + STAGE(kc & 1);
        uint8_t* lb = hb + 16384;
#pragma unroll
        for (int g = 0; g < 4; g++) {
            uint4 hi4, lo4;
            split8(pf[2 * g], pf[2 * g + 1], hi4, lo4);
            uint32_t off = SWZ((uint32_t)(r * 128 + h * 64 + g * 16));
            *reinterpret_cast<uint4*>(hb + off) = hi4;
            *reinterpret_cast<uint4*>(lb + off) = lo4;
        }
        __syncthreads();
        if (kc + 1 < 64) {
#pragma unroll
            for (int p = 0; p < 8; p++)
                pf[p] = *reinterpret_cast<const float4*>(rowp + (kc + 1) * 64 + h * 32 + p * 4);
        }
        const uint32_t hbu = smb + STAGE(kc & 1);
        const uint32_t lbu = hbu + 16384u;
#pragma unroll
        for (int kk2 = 0; kk2 < 2; kk2++) {
            const int c16 = h1 * 2 + kk2;
            uint32_t ah[2][4], al[2][4], bh[4][4], bl[4][4];
#pragma unroll
            for (int mt = 0; mt < 2; mt++) {
                int rowA = m0abs + mt * 16 + (lane & 15);
                int ch = c16 * 2 + (lane >> 4);
                uint32_t off = SWZ((uint32_t)(rowA * 128 + ch * 16));
                ldsm4(ah[mt], hbu + off);
                ldsm4(al[mt], lbu + off);
            }
#pragma unroll
            for (int bt = 0; bt < 4; bt++) {
                int rowB = n0 + bt * 16 + ((lane >> 4) & 1) * 8 + (lane & 7);
                int ch = c16 * 2 + ((lane >> 3) & 1);
                uint32_t off = SWZ((uint32_t)(rowB * 128 + ch * 16));
                ldsm4(bh[bt], hbu + off);
                ldsm4(bl[bt], lbu + off);
            }
#pragma unroll
            for (int mt = 0; mt < 2; mt++)
#pragma unroll
                for (int nt = 0; nt < 8; nt++) {
                    uint32_t b0h = bh[nt >> 1][(nt & 1) * 2];
                    uint32_t b1h = bh[nt >> 1][(nt & 1) * 2 + 1];
                    uint32_t b0l = bl[nt >> 1][(nt & 1) * 2];
                    uint32_t b1l = bl[nt >> 1][(nt & 1) * 2 + 1];
                    mma16816(acc[mt][nt], ah[mt], b0h, b1h);
                    mma16816(acc[mt][nt], ah[mt], b0l, b1l);
                    mma16816(acc[mt][nt], al[mt], b0h, b1h);
                }
        }
    }

    __syncthreads();   // stages dead; E may alias stage 0

    // E (64x132, CTA-relative rows) = sum of the two k-half partials
    {
        float* E = reinterpret_cast<float*>(sm);
        if (h1 == 1) {
#pragma unroll
            for (int mt = 0; mt < 2; mt++)
#pragma unroll
                for (int nt = 0; nt < 8; nt++) {
                    int row = tm * 32 + mt * 16 + (lane >> 2);
                    int col = n0 + nt * 8 + (lane & 3) * 2;
                    *reinterpret_cast<float2*>(&E[row * ESTR + col]) =
                        make_float2(acc[mt][nt][0], acc[mt][nt][1]);
                    *reinterpret_cast<float2*>(&E[(row + 8) * ESTR + col]) =
                        make_float2(acc[mt][nt][2], acc[mt][nt][3]);
                }
        }
        __syncthreads();
        if (h1 == 0) {
#pragma unroll
            for (int mt = 0; mt < 2; mt++)
#pragma unroll
                for (int nt = 0; nt < 8; nt++) {
                    int row = tm * 32 + mt * 16 + (lane >> 2);
                    int col = n0 + nt * 8 + (lane & 3) * 2;
                    float2 e0 = *reinterpret_cast<float2*>(&E[row * ESTR + col]);
                    float2 e1 = *reinterpret_cast<float2*>(&E[(row + 8) * ESTR + col]);
                    e0.x += acc[mt][nt][0]; e0.y += acc[mt][nt][1];
                    e1.x += acc[mt][nt][2]; e1.y += acc[mt][nt][3];
                    *reinterpret_cast<float2*>(&E[row * ESTR + col]) = e0;
                    *reinterpret_cast<float2*>(&E[(row + 8) * ESTR + col]) = e1;
                }
        }
    }
    __syncthreads();

    // prefetch phase-2 chunk 0 while softmin runs
    float4 pf2[8];
#pragma unroll
    for (int p = 0; p < 8; p++)
        pf2[p] = *reinterpret_cast<const float4*>(rowp + h * 32 + p * 4);

    // ===== Softmin over this CTA's 64 rows: A_hi[c_rel][m] = bf16(exp(min - E)) =====
    if (tid < 64) {
        const int cr = tid;
        const float* Er = reinterpret_cast<const float*>(sm) + cr * ESTR;
        float mn = Er[0];
#pragma unroll 4
        for (int m = 1; m < 128; m++) mn = fminf(mn, Er[m]);
        float sum = 0.f;
#pragma unroll
        for (int mg = 0; mg < 16; mg++) {
            float p[8];
#pragma unroll
            for (int q = 0; q < 8; q++) {
                p[q] = __expf(mn - Er[mg * 8 + q]);
                sum += p[q];
            }
            uint4 hi4;
            hi4.x = pack2hi(p[0], p[1]);
            hi4.y = pack2hi(p[2], p[3]);
            hi4.z = pack2hi(p[4], p[5]);
            hi4.w = pack2hi(p[6], p[7]);
            const int m = mg * 8;
            uint32_t off = AOFF + (uint32_t)(m >> 6) * 8192u
                         + SWZ((uint32_t)(cr * 128 + (m & 63) * 2));
            *reinterpret_cast<uint4*>(sm + off) = hi4;
        }
        reinterpret_cast<float*>(sm + IVOFF)[cr] = gamma[0] / sum;
    }
    __syncthreads();

    // ===== Phase 2: out rows [64hc,64hc+64) = A_hi * V_hi; A in regs; 32x16 warp tiles =====
    const int wm2 = wid & 1;
    const int wn2 = wid >> 1;       // 0..3 (16-wide s blocks)
    const int m0rel = wm2 * 32;

    uint32_t ahr[2][8][4];
#pragma unroll
    for (int mt = 0; mt < 2; mt++)
#pragma unroll
        for (int kk = 0; kk < 8; kk++) {
            int rowA = m0rel + mt * 16 + (lane & 15);
            int chb = (kk & 3) * 2 + (lane >> 4);
            uint32_t off = AOFF + (uint32_t)(kk >> 2) * 8192u
                         + SWZ((uint32_t)(rowA * 128 + chb * 16));
            ldsm4(ahr[mt][kk], smb + off);
        }

    const float* ivp = reinterpret_cast<const float*>(sm + IVOFF);

    for (int sc = 0; sc < 64; sc++) {
        uint8_t* hb = sm + STAGE(sc & 1);
        uint8_t* lb = hb + 16384;
#pragma unroll
        for (int g = 0; g < 4; g++) {
            uint4 hi4, lo4;
            split8(pf2[2 * g], pf2[2 * g + 1], hi4, lo4);
            uint32_t off = SWZ((uint32_t)(r * 128 + h * 64 + g * 16));
            *reinterpret_cast<uint4*>(hb + off) = hi4;
            *reinterpret_cast<uint4*>(lb + off) = lo4;
        }
        __syncthreads();
        if (sc + 1 < 64) {
#pragma unroll
            for (int p = 0; p < 8; p++)
                pf2[p] = *reinterpret_cast<const float4*>(rowp + (sc + 1) * 64 + h * 32 + p * 4);
        }

        float c2[2][2][4];
#pragma unroll
        for (int mt = 0; mt < 2; mt++)
#pragma unroll
            for (int nt = 0; nt < 2; nt++)
#pragma unroll
                for (int q = 0; q < 4; q++) c2[mt][nt][q] = 0.f;

        const uint32_t Bh = smb + STAGE(sc & 1);
#pragma unroll
        for (int kk = 0; kk < 8; kk++) {
            uint32_t bh[4];
            int rowB = kk * 16 + (lane & 15);
            int sch = wn2 * 2 + (lane >> 4);
            ldsm4t(bh, Bh + SWZ((uint32_t)(rowB * 128 + sch * 16)));
#pragma unroll
            for (int mt = 0; mt < 2; mt++)
#pragma unroll
                for (int nt = 0; nt < 2; nt++)
                    mma16816(c2[mt][nt], ahr[mt][kk], bh[nt * 2], bh[nt * 2 + 1]);
        }

        // epilogue: out[c][s] = inv[c]*acc + V[c][s]  (V = hi + lo from stage)
#pragma unroll
        for (int mt = 0; mt < 2; mt++)
#pragma unroll
            for (int nt = 0; nt < 2; nt++) {
                int rowrel = m0rel + mt * 16 + (lane >> 2);
                int scol = wn2 * 16 + nt * 8 + (lane & 3) * 2;
#pragma unroll
                for (int half = 0; half < 2; half++) {
                    int cr = rowrel + half * 8;
                    int ca = hc * 64 + cr;
                    float iv = ivp[cr];
                    uint32_t offv = SWZ((uint32_t)(ca * 128 + scol * 2));
                    float2 vh = bfpair(*reinterpret_cast<const uint32_t*>(hb + offv));
                    float2 vl = bfpair(*reinterpret_cast<const uint32_t*>(lb + offv));
                    float2 o;
                    o.x = fmaf(c2[mt][nt][half * 2 + 0], iv, vh.x + vl.x);
                    o.y = fmaf(c2[mt][nt][half * 2 + 1], iv, vh.y + vl.y);
                    *reinterpret_cast<float2*>(outbase + (size_t)ca * SSk + sc * 64 + scol) = o;
                }
            }
    }
}

extern "C" void kernel_launch(void* const* d_in, const int* in_sizes, int n_in,
                              void* d_out, int out_size)
{
    const float* x     = (const float*)d_in[0];
    const float* gamma = (const float*)d_in[1];
    float* out = (float*)d_out;

    cudaFuncSetAttribute(cam_mma7_kernel,
                         cudaFuncAttributeMaxDynamicSharedMemorySize, SMEMSZ);
    cam_mma7_kernel<<<256, 256, SMEMSZ>>>(x, gamma, out);
}

// round 14
// speedup vs baseline: 2.4144x; 2.4144x over previous
#include <cuda_runtime.h>
#include <cuda_fp16.h>
#include <cstdint>

// Problem constants
#define CCk 128
#define DDk 32
#define SSk 4096

// ---------------- smem byte layout ----------------
// Phase-1 stages (48KB each): stage s at s*48KB:
//   H [128][64] fp16 (16KB) + Hhalf (+16KB) + L (+32KB).
// Phase-2 reuses: hi at STG(s), lo at STG(s)+16KB.
// acc/E f32 [128][129] at 0 (66048 B) — aliases stages (dead when E live).
// A_hi (fp16 K-major, two 16KB blocks by m>>6) at 98304.
// inv[128] f32 at 131072.
#define STG(s)   ((uint32_t)(s) * 49152u)
#define ESTR     129
#define AOFF     98304u
#define IVOFF    131072u
#define SMEMSZ   (IVOFF + 512u)

#define SWZ(o) ((o) ^ (((o) >> 3) & 0x70u))

static __device__ __forceinline__ uint32_t s2u(const void* p) {
    uint32_t a;
    asm("{ .reg .u64 t; cvta.to.shared.u64 t, %1; cvt.u32.u64 %0, t; }"
        : "=r"(a) : "l"(p));
    return a;
}

static __device__ __forceinline__ void ldsm4(uint32_t* r, uint32_t addr) {
    asm volatile("ldmatrix.sync.aligned.m8n8.x4.shared.b16 {%0,%1,%2,%3}, [%4];"
        : "=r"(r[0]), "=r"(r[1]), "=r"(r[2]), "=r"(r[3]) : "r"(addr));
}
static __device__ __forceinline__ void ldsm4t(uint32_t* r, uint32_t addr) {
    asm volatile("ldmatrix.sync.aligned.m8n8.x4.trans.shared.b16 {%0,%1,%2,%3}, [%4];"
        : "=r"(r[0]), "=r"(r[1]), "=r"(r[2]), "=r"(r[3]) : "r"(addr));
}
static __device__ __forceinline__ void mma16816(float* c, const uint32_t* a,
                                                uint32_t b0, uint32_t b1) {
    asm volatile(
        "mma.sync.aligned.m16n8k16.row.col.f32.f16.f16.f32 "
        "{%0,%1,%2,%3}, {%4,%5,%6,%7}, {%8,%9}, {%0,%1,%2,%3};"
        : "+f"(c[0]), "+f"(c[1]), "+f"(c[2]), "+f"(c[3])
        : "r"(a[0]), "r"(a[1]), "r"(a[2]), "r"(a[3]), "r"(b0), "r"(b1));
}

// fp16 split: hp = f16x2(f0,f1) (f0 low), lp = residual
static __device__ __forceinline__ void split2(float f0, float f1, uint32_t& hp, uint32_t& lp) {
    __half2 h = __floats2half2_rn(f0, f1);
    hp = *reinterpret_cast<uint32_t*>(&h);
    float2 hf = __half22float2(h);
    __half2 l = __floats2half2_rn(f0 - hf.x, f1 - hf.y);
    lp = *reinterpret_cast<uint32_t*>(&l);
}
static __device__ __forceinline__ uint32_t pack2(float f0, float f1) {
    __half2 h = __floats2half2_rn(f0, f1);
    return *reinterpret_cast<uint32_t*>(&h);
}
static __device__ __forceinline__ uint32_t halve2(uint32_t w) {
    __half2 h = *reinterpret_cast<__half2*>(&w);
    __half2 r = __hmul2(h, __floats2half2_rn(0.5f, 0.5f));
    return *reinterpret_cast<uint32_t*>(&r);
}
static __device__ __forceinline__ void split8(float4 a, float4 b, uint4& hi, uint4& lo) {
    split2(a.x, a.y, hi.x, lo.x);
    split2(a.z, a.w, hi.y, lo.y);
    split2(b.x, b.y, hi.z, lo.z);
    split2(b.z, b.w, hi.w, lo.w);
}
static __device__ __forceinline__ float2 hfpair(uint32_t w) {
    __half2 h = *reinterpret_cast<__half2*>(&w);
    return __half22float2(h);
}

__global__ __launch_bounds__(256, 1)
void cam_mma8_kernel(const float* __restrict__ x,
                     const float* __restrict__ gamma,
                     float* __restrict__ out)
{
    extern __shared__ __align__(1024) uint8_t sm[];
    const uint32_t smb = s2u(sm);

    const int tid  = threadIdx.x;
    const int lane = tid & 31;
    const int wid  = tid >> 5;
    const int wm   = wid & 3;      // m block: rows 32*wm
    const int wn   = wid >> 2;     // n block (64-wide in phase 1)
    const int m0   = wm * 32;
    const int n0   = wn * 64;

    const int n = blockIdx.x;
    const int b = n / DDk, d = n % DDk;
    const float* xbase = x + ((size_t)(b * CCk) * DDk + d) * (size_t)SSk;
    const size_t cstride = (size_t)DDk * SSk;
    float* outbase = out + (size_t)n * CCk * SSk;

    const int r = tid >> 1, h = tid & 1;   // conversion mapping: row r, half h
    const float* rowp = xbase + (size_t)r * cstride;

    // ====== Phase 1: acc = (H/2)*H^T + H*L^T  (then E = acc + acc^T, exact) ======
    float acc[2][8][4];
#pragma unroll
    for (int mt = 0; mt < 2; mt++)
#pragma unroll
        for (int nt = 0; nt < 8; nt++)
#pragma unroll
            for (int q = 0; q < 4; q++) acc[mt][nt][q] = 0.f;

    float4 pf[8];
#pragma unroll
    for (int p = 0; p < 8; p++)
        pf[p] = *reinterpret_cast<const float4*>(rowp + h * 32 + p * 4);

    for (int kc = 0; kc < 64; kc++) {
        uint8_t* hb = sm + STG(kc & 1);            // H
        uint8_t* qb = hb + 16384;                  // Hhalf
        uint8_t* lb = hb + 32768;                  // L
#pragma unroll
        for (int g = 0; g < 4; g++) {
            uint4 hi4, lo4;
            split8(pf[2 * g], pf[2 * g + 1], hi4, lo4);
            uint4 hf4;
            hf4.x = halve2(hi4.x);
            hf4.y = halve2(hi4.y);
            hf4.z = halve2(hi4.z);
            hf4.w = halve2(hi4.w);
            uint32_t off = SWZ((uint32_t)(r * 128 + h * 64 + g * 16));
            *reinterpret_cast<uint4*>(hb + off) = hi4;
            *reinterpret_cast<uint4*>(qb + off) = hf4;
            *reinterpret_cast<uint4*>(lb + off) = lo4;
        }
        __syncthreads();
        if (kc + 1 < 64) {
#pragma unroll
            for (int p = 0; p < 8; p++)
                pf[p] = *reinterpret_cast<const float4*>(rowp + (kc + 1) * 64 + h * 32 + p * 4);
        }
        const uint32_t hbu = smb + STG(kc & 1);
        const uint32_t qbu = hbu + 16384u;
        const uint32_t lbu = hbu + 32768u;
#pragma unroll
        for (int kk = 0; kk < 4; kk++) {
            uint32_t ah[2][4], bq[4][4], bl[4][4];
#pragma unroll
            for (int mt = 0; mt < 2; mt++) {
                int rowA = m0 + mt * 16 + (lane & 15);
                int ch = kk * 2 + (lane >> 4);
                ldsm4(ah[mt], hbu + SWZ((uint32_t)(rowA * 128 + ch * 16)));
            }
#pragma unroll
            for (int bt = 0; bt < 4; bt++) {
                int rowB = n0 + bt * 16 + ((lane >> 4) & 1) * 8 + (lane & 7);
                int ch = kk * 2 + ((lane >> 3) & 1);
                uint32_t off = SWZ((uint32_t)(rowB * 128 + ch * 16));
                ldsm4(bq[bt], qbu + off);
                ldsm4(bl[bt], lbu + off);
            }
#pragma unroll
            for (int mt = 0; mt < 2; mt++)
#pragma unroll
                for (int nt = 0; nt < 8; nt++) {
                    uint32_t q0 = bq[nt >> 1][(nt & 1) * 2];
                    uint32_t q1 = bq[nt >> 1][(nt & 1) * 2 + 1];
                    uint32_t l0 = bl[nt >> 1][(nt & 1) * 2];
                    uint32_t l1 = bl[nt >> 1][(nt & 1) * 2 + 1];
                    mma16816(acc[mt][nt], ah[mt], q0, q1);   // (1/2) H H^T
                    mma16816(acc[mt][nt], ah[mt], l0, l1);   // H L^T
                }
        }
    }

    __syncthreads();   // stages dead; acc spill region may alias them

    // spill acc to smem (f32 [128][129], scalar stores)
    {
        float* E = reinterpret_cast<float*>(sm);
#pragma unroll
        for (int mt = 0; mt < 2; mt++)
#pragma unroll
            for (int nt = 0; nt < 8; nt++) {
                int row = m0 + mt * 16 + (lane >> 2);
                int col = n0 + nt * 8 + (lane & 3) * 2;
                E[row * ESTR + col]           = acc[mt][nt][0];
                E[row * ESTR + col + 1]       = acc[mt][nt][1];
                E[(row + 8) * ESTR + col]     = acc[mt][nt][2];
                E[(row + 8) * ESTR + col + 1] = acc[mt][nt][3];
            }
    }
    __syncthreads();

    // prefetch phase-2 chunk 0 while softmin runs
    float4 pf2[8];
#pragma unroll
    for (int p = 0; p < 8; p++)
        pf2[p] = *reinterpret_cast<const float4*>(rowp + h * 32 + p * 4);

    // ====== Softmin with E[c][m] = acc[c][m] + acc[m][c]; write A (fp16) ======
    if (tid < 128) {
        const int c = tid;
        const float* Ea = reinterpret_cast<const float*>(sm);
        float mn = 3.4e38f;
#pragma unroll 4
        for (int m = 0; m < 128; m++)
            mn = fminf(mn, Ea[c * ESTR + m] + Ea[m * ESTR + c]);
        float sum = 0.f;
#pragma unroll
        for (int mg = 0; mg < 16; mg++) {
            float p[8];
#pragma unroll
            for (int q = 0; q < 8; q++) {
                int m = mg * 8 + q;
                p[q] = __expf(mn - (Ea[c * ESTR + m] + Ea[m * ESTR + c]));
                sum += p[q];
            }
            uint4 hi4;
            hi4.x = pack2(p[0], p[1]);
            hi4.y = pack2(p[2], p[3]);
            hi4.z = pack2(p[4], p[5]);
            hi4.w = pack2(p[6], p[7]);
            const int m = mg * 8;
            uint32_t off = AOFF + (uint32_t)(m >> 6) * 16384u
                         + SWZ((uint32_t)(c * 128 + (m & 63) * 2));
            *reinterpret_cast<uint4*>(sm + off) = hi4;
        }
        reinterpret_cast<float*>(sm + IVOFF)[c] = gamma[0] / sum;
    }
    __syncthreads();

    // ====== Phase 2: out = A_hi * V_hi. A in regs, 1-term, fp16 ======
    uint32_t ahr[2][8][4];
#pragma unroll
    for (int mt = 0; mt < 2; mt++)
#pragma unroll
        for (int kk = 0; kk < 8; kk++) {
            int rowA = m0 + mt * 16 + (lane & 15);
            int chb = (kk & 3) * 2 + (lane >> 4);
            uint32_t off = AOFF + (uint32_t)(kk >> 2) * 16384u
                         + SWZ((uint32_t)(rowA * 128 + chb * 16));
            ldsm4(ahr[mt][kk], smb + off);
        }

    const float* ivp = reinterpret_cast<const float*>(sm + IVOFF);

    for (int sc = 0; sc < 64; sc++) {
        uint8_t* hb = sm + STG(sc & 1);
        uint8_t* lb = hb + 16384;
#pragma unroll
        for (int g = 0; g < 4; g++) {
            uint4 hi4, lo4;
            split8(pf2[2 * g], pf2[2 * g + 1], hi4, lo4);
            uint32_t off = SWZ((uint32_t)(r * 128 + h * 64 + g * 16));
            *reinterpret_cast<uint4*>(hb + off) = hi4;
            *reinterpret_cast<uint4*>(lb + off) = lo4;
        }
        __syncthreads();
        if (sc + 1 < 64) {
#pragma unroll
            for (int p = 0; p < 8; p++)
                pf2[p] = *reinterpret_cast<const float4*>(rowp + (sc + 1) * 64 + h * 32 + p * 4);
        }

        float c2[2][4][4];
#pragma unroll
        for (int mt = 0; mt < 2; mt++)
#pragma unroll
            for (int nt = 0; nt < 4; nt++)
#pragma unroll
                for (int q = 0; q < 4; q++) c2[mt][nt][q] = 0.f;

        const uint32_t Bh = smb + STG(sc & 1);
#pragma unroll
        for (int kk = 0; kk < 8; kk++) {
            uint32_t bh[2][4];
#pragma unroll
            for (int bt = 0; bt < 2; bt++) {
                int rowB = kk * 16 + (lane & 15);
                int sch = wn * 4 + bt * 2 + (lane >> 4);
                ldsm4t(bh[bt], Bh + SWZ((uint32_t)(rowB * 128 + sch * 16)));
            }
#pragma unroll
            for (int mt = 0; mt < 2; mt++)
#pragma unroll
                for (int nt = 0; nt < 4; nt++)
                    mma16816(c2[mt][nt], ahr[mt][kk],
                             bh[nt >> 1][(nt & 1) * 2], bh[nt >> 1][(nt & 1) * 2 + 1]);
        }

        // epilogue: out[c][s] = inv[c]*acc + V[c][s]  (V = hi + lo, ~exact)
#pragma unroll
        for (int mt = 0; mt < 2; mt++)
#pragma unroll
            for (int nt = 0; nt < 4; nt++) {
                int row = m0 + mt * 16 + (lane >> 2);
                int scol = wn * 32 + nt * 8 + (lane & 3) * 2;
#pragma unroll
                for (int half = 0; half < 2; half++) {
                    int c = row + half * 8;
                    float iv = ivp[c];
                    uint32_t offv = SWZ((uint32_t)(c * 128 + scol * 2));
                    float2 vh = hfpair(*reinterpret_cast<const uint32_t*>(hb + offv));
                    float2 vl = hfpair(*reinterpret_cast<const uint32_t*>(lb + offv));
                    float2 o;
                    o.x = fmaf(c2[mt][nt][half * 2 + 0], iv, vh.x + vl.x);
                    o.y = fmaf(c2[mt][nt][half * 2 + 1], iv, vh.y + vl.y);
                    *reinterpret_cast<float2*>(outbase + (size_t)c * SSk + sc * 64 + scol) = o;
                }
            }
    }
}

extern "C" void kernel_launch(void* const* d_in, const int* in_sizes, int n_in,
                              void* d_out, int out_size)
{
    const float* x     = (const float*)d_in[0];
    const float* gamma = (const float*)d_in[1];
    float* out = (float*)d_out;

    cudaFuncSetAttribute(cam_mma8_kernel,
                         cudaFuncAttributeMaxDynamicSharedMemorySize, SMEMSZ);
    cam_mma8_kernel<<<128, 256, SMEMSZ>>>(x, gamma, out);
}